// round 7
// baseline (speedup 1.0000x reference)
#include <cuda_runtime.h>
#include <cuda_bf16.h>
#include <math.h>
#include <stdint.h>

#define NN 100000
#define EE 1600000
#define NB_MAX 128

// ---------------- device scratch ----------------
__device__ int   g_cnt[NN];
__device__ int   g_cursor[NN];
__device__ int   g_rowptr[NN + 1];
__device__ int   g_col[EE];
__device__ int   g_bsum[NB_MAX];
__device__ float g_dinv[NN];
__device__ float g_hs[(size_t)NN * 64];
__device__ float g_ag[(size_t)NN * 64];

// ---------------- preprocessing ----------------
__global__ void zero_kernel(int n) {
    int i = blockIdx.x * blockDim.x + threadIdx.x;
    if (i < n) { g_cnt[i] = 0; g_cursor[i] = 0; }
}
__global__ void hist_kernel(const int* __restrict__ dst, int e) {
    int i = blockIdx.x * blockDim.x + threadIdx.x;
    if (i < e) atomicAdd(&g_cnt[__ldg(&dst[i])], 1);
}
__global__ void scan_blocks(int n) {
    __shared__ int wsum[32];
    int tid = threadIdx.x, lane = tid & 31, wid = tid >> 5;
    int gid = blockIdx.x * 1024 + tid;
    int v = (gid < n) ? g_cnt[gid] : 0;
    int x = v;
    #pragma unroll
    for (int off = 1; off < 32; off <<= 1) {
        int t = __shfl_up_sync(0xffffffffu, x, off);
        if (lane >= off) x += t;
    }
    if (lane == 31) wsum[wid] = x;
    __syncthreads();
    if (wid == 0) {
        int s = wsum[lane];
        #pragma unroll
        for (int off = 1; off < 32; off <<= 1) {
            int t = __shfl_up_sync(0xffffffffu, s, off);
            if (lane >= off) s += t;
        }
        wsum[lane] = s;
    }
    __syncthreads();
    int incl = x + (wid > 0 ? wsum[wid - 1] : 0);
    if (gid < n) g_rowptr[gid] = incl - v;
    if (tid == 1023) g_bsum[blockIdx.x] = incl;
}
// finalize: per-block re-derived scan of block sums (nb<=128), add offsets, dinv
__global__ void finalize_kernel(int n, int nb) {
    __shared__ int sboff[NB_MAX];
    __shared__ int stot;
    int tid = threadIdx.x;
    if (tid < 32) {
        int base = tid * 4;
        int v0 = (base + 0 < nb) ? g_bsum[base + 0] : 0;
        int v1 = (base + 1 < nb) ? g_bsum[base + 1] : 0;
        int v2 = (base + 2 < nb) ? g_bsum[base + 2] : 0;
        int v3 = (base + 3 < nb) ? g_bsum[base + 3] : 0;
        int s0 = v0, s1 = s0 + v1, s2 = s1 + v2, s3 = s2 + v3;
        int c = s3;
        #pragma unroll
        for (int off = 1; off < 32; off <<= 1) {
            int t = __shfl_up_sync(0xffffffffu, c, off);
            if (tid >= off) c += t;
        }
        int excl = c - s3;
        sboff[base + 0] = excl;
        sboff[base + 1] = excl + s0;
        sboff[base + 2] = excl + s1;
        sboff[base + 3] = excl + s2;
        if (tid == 31) stot = c;
    }
    __syncthreads();
    int i = blockIdx.x * blockDim.x + tid;
    if (i < n) {
        g_rowptr[i] += sboff[i >> 10];
        g_dinv[i] = rsqrtf((float)(g_cnt[i] + 1));
    }
    if (blockIdx.x == 0 && tid == 0) g_rowptr[n] = stot;
}
__global__ void scatter_kernel(const int* __restrict__ src,
                               const int* __restrict__ dst, int e) {
    int i = blockIdx.x * blockDim.x + threadIdx.x;
    if (i < e) {
        int d = __ldg(&dst[i]);
        int pos = g_rowptr[d] + atomicAdd(&g_cursor[d], 1);
        g_col[pos] = __ldg(&src[i]);
    }
}

// ---------------- mma helpers ----------------
__device__ __forceinline__ uint32_t pack_bf2(float a, float b) {
    __nv_bfloat162 t = __floats2bfloat162_rn(a, b);
    return *reinterpret_cast<uint32_t*>(&t);
}
__device__ __forceinline__ uint32_t lo_pack(float2 v, uint32_t h) {
    float hx = __uint_as_float(h << 16);
    float hy = __uint_as_float(h & 0xffff0000u);
    return pack_bf2(v.x - hx, v.y - hy);
}
__device__ __forceinline__ void mma_bf16(float* c, uint32_t a0, uint32_t a1,
                                         uint32_t a2, uint32_t a3,
                                         uint32_t b0, uint32_t b1) {
    asm volatile(
        "mma.sync.aligned.m16n8k16.row.col.f32.bf16.bf16.f32 "
        "{%0,%1,%2,%3}, {%4,%5,%6,%7}, {%8,%9}, {%0,%1,%2,%3};"
        : "+f"(c[0]), "+f"(c[1]), "+f"(c[2]), "+f"(c[3])
        : "r"(a0), "r"(a1), "r"(a2), "r"(a3), "r"(b0), "r"(b1));
}
__device__ __forceinline__ void ldsm_x4(uint32_t& r0, uint32_t& r1,
                                        uint32_t& r2, uint32_t& r3, uint32_t a) {
    asm volatile("ldmatrix.sync.aligned.m8n8.x4.shared.b16 {%0,%1,%2,%3}, [%4];"
                 : "=r"(r0), "=r"(r1), "=r"(r2), "=r"(r3) : "r"(a));
}

// ---------------- GEMM: smem A + smem B, all fragments via ldmatrix ----------------
// out[r,c] = sum_k X[r,k] W[k,c] + bias?[c]
// CTA: 256 threads / 8 warps, M-tile 128; warp: 16 rows x full N. K=KS*16, N=NT*8.
template <int KS, int NT>
__global__ void __launch_bounds__(256)
gemm_mma_kernel(const float* __restrict__ X, const float* __restrict__ W,
                float* __restrict__ out, int M, const float* __restrict__ bias) {
    constexpr int K  = KS * 16;
    constexpr int Nn = NT * 8;
    constexpr int PA = K + 8;   // pitch: 16B-aligned rows, ldmatrix conflict-free
    extern __shared__ __nv_bfloat16 sm[];
    __nv_bfloat16* aHi = sm;
    __nv_bfloat16* aLo = aHi + 128 * PA;
    __nv_bfloat16* wHi = aLo + 128 * PA;
    __nv_bfloat16* wLo = wHi + Nn * PA;

    int tid = threadIdx.x, lane = tid & 31, wid = tid >> 5;
    int rowbase = blockIdx.x * 128;

    // ---- A tile fill: coalesced float4, fp32 -> (hi, lo) bf16 ----
    constexpr int C4 = K / 4;
    #pragma unroll
    for (int idx = tid; idx < 128 * C4; idx += 256) {
        int r = idx / C4;
        int c = (idx % C4) * 4;
        float4 v = make_float4(0.f, 0.f, 0.f, 0.f);
        int gr = rowbase + r;
        if (gr < M) v = __ldg((const float4*)(X + (size_t)gr * K + c));
        uint32_t h01 = pack_bf2(v.x, v.y);
        uint32_t h23 = pack_bf2(v.z, v.w);
        int o = r * PA + c;
        *(uint32_t*)(aHi + o)     = h01;
        *(uint32_t*)(aHi + o + 2) = h23;
        *(uint32_t*)(aLo + o)     = lo_pack(make_float2(v.x, v.y), h01);
        *(uint32_t*)(aLo + o + 2) = lo_pack(make_float2(v.z, v.w), h23);
    }
    // ---- W tile fill: transpose to Wt[n][k], hi/lo ----
    #pragma unroll
    for (int idx = tid; idx < K * Nn; idx += 256) {
        int k = idx / Nn, n2 = idx - k * Nn;
        float v = __ldg(&W[idx]);
        __nv_bfloat16 h = __float2bfloat16(v);
        __nv_bfloat16 l = __float2bfloat16(v - __bfloat162float(h));
        wHi[n2 * PA + k] = h;
        wLo[n2 * PA + k] = l;
    }
    __syncthreads();

    int gp = lane >> 2, tig = lane & 3;

    // A ldmatrix lane address: mats ordered (m0k0),(m8k0),(m0k8),(m8k8)
    int rowOffA = (lane & 7) + ((lane & 8) ? 8 : 0);
    int kOffA   = (lane & 16) ? 8 : 0;
    uint32_t aHiA = (uint32_t)__cvta_generic_to_shared(aHi) +
                    (uint32_t)(((wid * 16 + rowOffA) * PA + kOffA) * 2);
    uint32_t aLoA = aHiA + (uint32_t)(128 * PA * 2);

    // B ldmatrix lane address (col-major fragment)
    int rowOffB = (lane & 7) + ((lane >> 4) << 3);
    int kOffB   = (lane & 8) ? 8 : 0;
    uint32_t wHiA = (uint32_t)__cvta_generic_to_shared(wHi) +
                    (uint32_t)((rowOffB * PA + kOffB) * 2);
    uint32_t wLoA = wHiA + (uint32_t)(Nn * PA * 2);

    float acc[NT][4];
    #pragma unroll
    for (int t = 0; t < NT; t++) {
        acc[t][0] = 0.f; acc[t][1] = 0.f; acc[t][2] = 0.f; acc[t][3] = 0.f;
    }

    #pragma unroll
    for (int kt = 0; kt < KS; kt++) {
        uint32_t koB = (uint32_t)(kt * 16 * 2);
        uint32_t ah0, ah1, ah2, ah3, al0, al1, al2, al3;
        ldsm_x4(ah0, ah1, ah2, ah3, aHiA + koB);
        ldsm_x4(al0, al1, al2, al3, aLoA + koB);
        #pragma unroll
        for (int nt2 = 0; nt2 < NT / 2; nt2++) {
            uint32_t off = (uint32_t)(nt2 * 16 * PA * 2) + koB;
            uint32_t bh0, bh1, bh2, bh3, bl0, bl1, bl2, bl3;
            ldsm_x4(bh0, bh1, bh2, bh3, wHiA + off);
            ldsm_x4(bl0, bl1, bl2, bl3, wLoA + off);
            mma_bf16(acc[2 * nt2],     ah0, ah1, ah2, ah3, bh0, bh1);
            mma_bf16(acc[2 * nt2],     ah0, ah1, ah2, ah3, bl0, bl1);
            mma_bf16(acc[2 * nt2],     al0, al1, al2, al3, bh0, bh1);
            mma_bf16(acc[2 * nt2 + 1], ah0, ah1, ah2, ah3, bh2, bh3);
            mma_bf16(acc[2 * nt2 + 1], ah0, ah1, ah2, ah3, bl2, bl3);
            mma_bf16(acc[2 * nt2 + 1], al0, al1, al2, al3, bh2, bh3);
        }
    }

    // ---- epilogue ----
    int r0 = rowbase + wid * 16 + gp;
    int r1 = r0 + 8;
    #pragma unroll
    for (int nt = 0; nt < NT; nt++) {
        int col = nt * 8 + tig * 2;
        float bx = 0.f, by = 0.f;
        if (bias) {
            float2 bv = __ldg((const float2*)&bias[col]);
            bx = bv.x; by = bv.y;
        }
        if (r0 < M)
            *(float2*)(out + (size_t)r0 * Nn + col) =
                make_float2(acc[nt][0] + bx, acc[nt][1] + by);
        if (r1 < M)
            *(float2*)(out + (size_t)r1 * Nn + col) =
                make_float2(acc[nt][2] + bx, acc[nt][3] + by);
    }
}

// ---------------- aggregation: 8 edges per warp-iter (4 per half) ----------------
__global__ void agg64_kernel(const float* __restrict__ hs,
                             const float* __restrict__ bias,
                             float* __restrict__ out,
                             int n, int relu) {
    int w = (blockIdx.x * blockDim.x + threadIdx.x) >> 5;
    if (w >= n) return;
    int lane = threadIdx.x & 31;
    int half = lane >> 4;
    int q = lane & 15;
    const float4* hs4 = (const float4*)hs;
    float ax = 0.f, ay = 0.f, az = 0.f, aw = 0.f;
    int s = g_rowptr[w], e = g_rowptr[w + 1];
    int i = s + half;
    for (; i + 6 < e; i += 8) {
        int u0 = __ldg(&g_col[i]);
        int u1 = __ldg(&g_col[i + 2]);
        int u2 = __ldg(&g_col[i + 4]);
        int u3 = __ldg(&g_col[i + 6]);
        float d0 = __ldg(&g_dinv[u0]);
        float d1 = __ldg(&g_dinv[u1]);
        float d2 = __ldg(&g_dinv[u2]);
        float d3 = __ldg(&g_dinv[u3]);
        float4 v0 = __ldg(&hs4[u0 * 16 + q]);
        float4 v1 = __ldg(&hs4[u1 * 16 + q]);
        float4 v2 = __ldg(&hs4[u2 * 16 + q]);
        float4 v3 = __ldg(&hs4[u3 * 16 + q]);
        ax += d0 * v0.x + d1 * v1.x + d2 * v2.x + d3 * v3.x;
        ay += d0 * v0.y + d1 * v1.y + d2 * v2.y + d3 * v3.y;
        az += d0 * v0.z + d1 * v1.z + d2 * v2.z + d3 * v3.z;
        aw += d0 * v0.w + d1 * v1.w + d2 * v2.w + d3 * v3.w;
    }
    for (; i < e; i += 2) {
        int u = __ldg(&g_col[i]);
        float d = __ldg(&g_dinv[u]);
        float4 v = __ldg(&hs4[u * 16 + q]);
        ax += d * v.x; ay += d * v.y; az += d * v.z; aw += d * v.w;
    }
    ax += __shfl_xor_sync(0xffffffffu, ax, 16);
    ay += __shfl_xor_sync(0xffffffffu, ay, 16);
    az += __shfl_xor_sync(0xffffffffu, az, 16);
    aw += __shfl_xor_sync(0xffffffffu, aw, 16);
    float4 sv = __ldg(&hs4[w * 16 + q]);
    float dv = __ldg(&g_dinv[w]);
    ax += sv.x * dv; ay += sv.y * dv; az += sv.z * dv; aw += sv.w * dv;
    ax *= dv; ay *= dv; az *= dv; aw *= dv;
    if (bias) {
        float4 bv = __ldg(&((const float4*)bias)[q]);
        ax += bv.x; ay += bv.y; az += bv.z; aw += bv.w;
    }
    if (relu) {
        ax = fmaxf(ax, 0.f); ay = fmaxf(ay, 0.f);
        az = fmaxf(az, 0.f); aw = fmaxf(aw, 0.f);
    }
    if (lane < 16) ((float4*)out)[w * 16 + q] = make_float4(ax, ay, az, aw);
}

// ---------------- host launcher ----------------
extern "C" void kernel_launch(void* const* d_in, const int* in_sizes, int n_in,
                              void* d_out, int out_size) {
    const float* x  = (const float*)d_in[0];
    const int*   ei = (const int*)d_in[1];
    const float* W1 = (const float*)d_in[2];
    const float* b1 = (const float*)d_in[3];
    const float* W2 = (const float*)d_in[4];
    const float* b2 = (const float*)d_in[5];
    const float* W3 = (const float*)d_in[6];
    const float* b3 = (const float*)d_in[7];
    float* out = (float*)d_out;

    int hid   = in_sizes[3];            // 64
    int odim  = in_sizes[7];            // 112
    int indim = in_sizes[2] / hid;      // 128
    int n     = in_sizes[0] / indim;    // 100000
    int e     = in_sizes[1] / 2;        // 1600000
    const int* src = ei;
    const int* dst = ei + e;

    float *hs_p, *ag_p;
    cudaGetSymbolAddress((void**)&hs_p, g_hs);
    cudaGetSymbolAddress((void**)&ag_p, g_ag);

    int nb = (n + 1023) / 1024;
    int aggBlocks = (n * 32 + 255) / 256;
    int gGrid = (n + 127) / 128;

    // smem bytes: (128 + Nn) * (K+8) * 2(hi/lo) * 2(bf16)
    auto smem_sz = [](int K, int Nn) { return (128 + Nn) * (K + 8) * 4; };
    cudaFuncSetAttribute(gemm_mma_kernel<8, 8>,
                         cudaFuncAttributeMaxDynamicSharedMemorySize, smem_sz(128, 64));
    cudaFuncSetAttribute(gemm_mma_kernel<4, 8>,
                         cudaFuncAttributeMaxDynamicSharedMemorySize, smem_sz(64, 64));
    cudaFuncSetAttribute(gemm_mma_kernel<4, 14>,
                         cudaFuncAttributeMaxDynamicSharedMemorySize, smem_sz(64, 112));

    zero_kernel<<<(n + 255) / 256, 256>>>(n);                          // 0
    hist_kernel<<<(e + 255) / 256, 256>>>(dst, e);                     // 1
    scan_blocks<<<nb, 1024>>>(n);                                      // 2
    // gemm1 is CSR-independent: at launch index 3 so ncu profiles it
    gemm_mma_kernel<8, 8><<<gGrid, 256, smem_sz(128, 64)>>>(x, W1, hs_p, n, nullptr);
    finalize_kernel<<<(n + 255) / 256, 256>>>(n, nb);                  // 4
    scatter_kernel<<<(e + 255) / 256, 256>>>(src, dst, e);             // 5

    agg64_kernel<<<aggBlocks, 256>>>(hs_p, b1, ag_p, n, 1);            // 6
    gemm_mma_kernel<4, 8><<<gGrid, 256, smem_sz(64, 64)>>>(ag_p, W2, hs_p, n, nullptr);
    agg64_kernel<<<aggBlocks, 256>>>(hs_p, b2, ag_p, n, 1);
    agg64_kernel<<<aggBlocks, 256>>>(ag_p, nullptr, hs_p, n, 0);
    gemm_mma_kernel<4, 14><<<gGrid, 256, smem_sz(64, 112)>>>(hs_p, W3, out, n, b3);
}

// round 8
// speedup vs baseline: 1.1302x; 1.1302x over previous
#include <cuda_runtime.h>
#include <cuda_bf16.h>
#include <cuda_fp16.h>
#include <math.h>
#include <stdint.h>

#define NN 100000
#define EE 1600000
#define NB_MAX 128

// ---------------- device scratch ----------------
__device__ int   g_cnt[NN];
__device__ int   g_cursor[NN];
__device__ int   g_rowptr[NN + 1];
__device__ int   g_col[EE];
__device__ int   g_bsum[NB_MAX];
__device__ float g_dinv[NN];
__device__ float g_hs[(size_t)NN * 64];
__device__ float g_ag[(size_t)NN * 64];

// ---------------- preprocessing ----------------
__global__ void zero_kernel(int n) {
    int i = blockIdx.x * blockDim.x + threadIdx.x;
    if (i < n) { g_cnt[i] = 0; g_cursor[i] = 0; }
}
__global__ void hist_kernel(const int* __restrict__ dst, int e) {
    int i = blockIdx.x * blockDim.x + threadIdx.x;
    if (i < e) atomicAdd(&g_cnt[__ldg(&dst[i])], 1);
}
__global__ void scan_blocks(int n) {
    __shared__ int wsum[32];
    int tid = threadIdx.x, lane = tid & 31, wid = tid >> 5;
    int gid = blockIdx.x * 1024 + tid;
    int v = (gid < n) ? g_cnt[gid] : 0;
    int x = v;
    #pragma unroll
    for (int off = 1; off < 32; off <<= 1) {
        int t = __shfl_up_sync(0xffffffffu, x, off);
        if (lane >= off) x += t;
    }
    if (lane == 31) wsum[wid] = x;
    __syncthreads();
    if (wid == 0) {
        int s = wsum[lane];
        #pragma unroll
        for (int off = 1; off < 32; off <<= 1) {
            int t = __shfl_up_sync(0xffffffffu, s, off);
            if (lane >= off) s += t;
        }
        wsum[lane] = s;
    }
    __syncthreads();
    int incl = x + (wid > 0 ? wsum[wid - 1] : 0);
    if (gid < n) g_rowptr[gid] = incl - v;
    if (tid == 1023) g_bsum[blockIdx.x] = incl;
}
__global__ void finalize_kernel(int n, int nb) {
    __shared__ int sboff[NB_MAX];
    __shared__ int stot;
    int tid = threadIdx.x;
    if (tid < 32) {
        int base = tid * 4;
        int v0 = (base + 0 < nb) ? g_bsum[base + 0] : 0;
        int v1 = (base + 1 < nb) ? g_bsum[base + 1] : 0;
        int v2 = (base + 2 < nb) ? g_bsum[base + 2] : 0;
        int v3 = (base + 3 < nb) ? g_bsum[base + 3] : 0;
        int s0 = v0, s1 = s0 + v1, s2 = s1 + v2, s3 = s2 + v3;
        int c = s3;
        #pragma unroll
        for (int off = 1; off < 32; off <<= 1) {
            int t = __shfl_up_sync(0xffffffffu, c, off);
            if (tid >= off) c += t;
        }
        int excl = c - s3;
        sboff[base + 0] = excl;
        sboff[base + 1] = excl + s0;
        sboff[base + 2] = excl + s1;
        sboff[base + 3] = excl + s2;
        if (tid == 31) stot = c;
    }
    __syncthreads();
    int i = blockIdx.x * blockDim.x + tid;
    if (i < n) {
        g_rowptr[i] += sboff[i >> 10];
        g_dinv[i] = rsqrtf((float)(g_cnt[i] + 1));
    }
    if (blockIdx.x == 0 && tid == 0) g_rowptr[n] = stot;
}
__global__ void scatter_kernel(const int* __restrict__ src,
                               const int* __restrict__ dst, int e) {
    int i = blockIdx.x * blockDim.x + threadIdx.x;
    if (i < e) {
        int d = __ldg(&dst[i]);
        int pos = g_rowptr[d] + atomicAdd(&g_cursor[d], 1);
        g_col[pos] = __ldg(&src[i]);
    }
}

// ---------------- fp16 mma helpers ----------------
__device__ __forceinline__ uint32_t h2_hi(float2 v) {
    __half2 h = __floats2half2_rn(v.x, v.y);
    return *reinterpret_cast<uint32_t*>(&h);
}
__device__ __forceinline__ uint32_t h2_lo(float2 v, uint32_t hbits) {
    __half2 h = *reinterpret_cast<__half2*>(&hbits);
    float2 b = __half22float2(h);
    __half2 l = __floats2half2_rn(v.x - b.x, v.y - b.y);
    return *reinterpret_cast<uint32_t*>(&l);
}
__device__ __forceinline__ void mma_f16(float* c, uint32_t a0, uint32_t a1,
                                        uint32_t a2, uint32_t a3,
                                        uint32_t b0, uint32_t b1) {
    asm volatile(
        "mma.sync.aligned.m16n8k16.row.col.f32.f16.f16.f32 "
        "{%0,%1,%2,%3}, {%4,%5,%6,%7}, {%8,%9}, {%0,%1,%2,%3};"
        : "+f"(c[0]), "+f"(c[1]), "+f"(c[2]), "+f"(c[3])
        : "r"(a0), "r"(a1), "r"(a2), "r"(a3), "r"(b0), "r"(b1));
}
__device__ __forceinline__ void ldsm_x4_trans(uint32_t& r0, uint32_t& r1,
                                              uint32_t& r2, uint32_t& r3, uint32_t a) {
    asm volatile("ldmatrix.sync.aligned.m8n8.x4.trans.shared.b16 {%0,%1,%2,%3}, [%4];"
                 : "=r"(r0), "=r"(r1), "=r"(r2), "=r"(r3) : "r"(a));
}

// ---------------- GEMM: fp16 2-pass (A split, B single), RG row-groups/warp ----
// out[r,c] = sum_k X[r,k] W[k,c] + bias?[c]
// CTA: 128 threads / 4 warps; warp tile: RG*16 rows x full N. K=KS*16, N=NT*8.
template <int KS, int NT, int RG>
__global__ void __launch_bounds__(128)
gemm_mma_kernel(const float* __restrict__ X, const float* __restrict__ W,
                float* __restrict__ out, int M, const float* __restrict__ bias) {
    constexpr int K  = KS * 16;
    constexpr int Nn = NT * 8;
    constexpr int PB = Nn + 8;          // fp16 pitch for W[k][n] (multiple of 8)
    constexpr int MT = 64 * RG;         // rows per CTA
    extern __shared__ __half wS[];

    int tid = threadIdx.x, lane = tid & 31, wid = tid >> 5;
    int rowbase = blockIdx.x * MT;

    // ---- W fill: straight copy W[k][n] fp32 -> fp16, coalesced ----
    constexpr int N4 = Nn / 4;
    #pragma unroll
    for (int idx = tid; idx < K * N4; idx += 128) {
        int k = idx / N4;
        int n4 = (idx - k * N4) * 4;
        float4 v = __ldg((const float4*)(W + (size_t)k * Nn + n4));
        __half2 h01 = __floats2half2_rn(v.x, v.y);
        __half2 h23 = __floats2half2_rn(v.z, v.w);
        *(__half2*)(wS + k * PB + n4)     = h01;
        *(__half2*)(wS + k * PB + n4 + 2) = h23;
    }
    __syncthreads();

    int gp = lane >> 2, tig = lane & 3;

    // A pointers: RG row-groups, rows (wid*16*RG + rg*16 + gp) and (+8)
    const float* xA[RG];
    const float* xB[RG];
    int rA[RG], rB[RG];
    #pragma unroll
    for (int rg = 0; rg < RG; rg++) {
        rA[rg] = rowbase + wid * (16 * RG) + rg * 16 + gp;
        rB[rg] = rA[rg] + 8;
        xA[rg] = X + (size_t)min(rA[rg], M - 1) * K + tig * 2;
        xB[rg] = X + (size_t)min(rB[rg], M - 1) * K + tig * 2;
    }

    // B ldmatrix.trans lane address: rows k, col n0 (+8 for hi lane half)
    int kRow = (lane & 7) + (((lane >> 3) & 1) << 3);   // 0..15
    int nCol = (lane >> 4) << 3;                        // 0 or 8
    uint32_t wBase = (uint32_t)__cvta_generic_to_shared(wS) +
                     (uint32_t)((kRow * PB + nCol) * 2);

    float acc[RG][NT][4];
    #pragma unroll
    for (int rg = 0; rg < RG; rg++)
        #pragma unroll
        for (int t = 0; t < NT; t++) {
            acc[rg][t][0] = 0.f; acc[rg][t][1] = 0.f;
            acc[rg][t][2] = 0.f; acc[rg][t][3] = 0.f;
        }

    #pragma unroll
    for (int kt = 0; kt < KS; kt++) {
        int ko = kt * 16;
        uint32_t ah[RG][4], al[RG][4];
        #pragma unroll
        for (int rg = 0; rg < RG; rg++) {
            float2 p0 = __ldg((const float2*)(xA[rg] + ko));
            float2 p1 = __ldg((const float2*)(xA[rg] + ko + 8));
            float2 p2 = __ldg((const float2*)(xB[rg] + ko));
            float2 p3 = __ldg((const float2*)(xB[rg] + ko + 8));
            ah[rg][0] = h2_hi(p0); al[rg][0] = h2_lo(p0, ah[rg][0]);
            ah[rg][1] = h2_hi(p2); al[rg][1] = h2_lo(p2, ah[rg][1]);
            ah[rg][2] = h2_hi(p1); al[rg][2] = h2_lo(p1, ah[rg][2]);
            ah[rg][3] = h2_hi(p3); al[rg][3] = h2_lo(p3, ah[rg][3]);
        }
        uint32_t kByte = (uint32_t)(ko * PB * 2);
        #pragma unroll
        for (int nt2 = 0; nt2 < NT / 2; nt2++) {
            uint32_t b0, b1, b2, b3;
            ldsm_x4_trans(b0, b1, b2, b3, wBase + kByte + (uint32_t)(nt2 * 16 * 2));
            #pragma unroll
            for (int rg = 0; rg < RG; rg++) {
                mma_f16(acc[rg][2 * nt2],     ah[rg][0], ah[rg][1], ah[rg][2], ah[rg][3], b0, b1);
                mma_f16(acc[rg][2 * nt2],     al[rg][0], al[rg][1], al[rg][2], al[rg][3], b0, b1);
                mma_f16(acc[rg][2 * nt2 + 1], ah[rg][0], ah[rg][1], ah[rg][2], ah[rg][3], b2, b3);
                mma_f16(acc[rg][2 * nt2 + 1], al[rg][0], al[rg][1], al[rg][2], al[rg][3], b2, b3);
            }
        }
    }

    // ---- epilogue ----
    #pragma unroll
    for (int rg = 0; rg < RG; rg++) {
        #pragma unroll
        for (int nt = 0; nt < NT; nt++) {
            int col = nt * 8 + tig * 2;
            float bx = 0.f, by = 0.f;
            if (bias) {
                float2 bv = __ldg((const float2*)&bias[col]);
                bx = bv.x; by = bv.y;
            }
            if (rA[rg] < M)
                *(float2*)(out + (size_t)rA[rg] * Nn + col) =
                    make_float2(acc[rg][nt][0] + bx, acc[rg][nt][1] + by);
            if (rB[rg] < M)
                *(float2*)(out + (size_t)rB[rg] * Nn + col) =
                    make_float2(acc[rg][nt][2] + bx, acc[rg][nt][3] + by);
        }
    }
}

// ---------------- aggregation: 8 edges per warp-iter (4 per half) ----------------
__global__ void agg64_kernel(const float* __restrict__ hs,
                             const float* __restrict__ bias,
                             float* __restrict__ out,
                             int n, int relu) {
    int w = (blockIdx.x * blockDim.x + threadIdx.x) >> 5;
    if (w >= n) return;
    int lane = threadIdx.x & 31;
    int half = lane >> 4;
    int q = lane & 15;
    const float4* hs4 = (const float4*)hs;
    float ax = 0.f, ay = 0.f, az = 0.f, aw = 0.f;
    int s = g_rowptr[w], e = g_rowptr[w + 1];
    int i = s + half;
    for (; i + 6 < e; i += 8) {
        int u0 = __ldg(&g_col[i]);
        int u1 = __ldg(&g_col[i + 2]);
        int u2 = __ldg(&g_col[i + 4]);
        int u3 = __ldg(&g_col[i + 6]);
        float d0 = __ldg(&g_dinv[u0]);
        float d1 = __ldg(&g_dinv[u1]);
        float d2 = __ldg(&g_dinv[u2]);
        float d3 = __ldg(&g_dinv[u3]);
        float4 v0 = __ldg(&hs4[u0 * 16 + q]);
        float4 v1 = __ldg(&hs4[u1 * 16 + q]);
        float4 v2 = __ldg(&hs4[u2 * 16 + q]);
        float4 v3 = __ldg(&hs4[u3 * 16 + q]);
        ax += d0 * v0.x + d1 * v1.x + d2 * v2.x + d3 * v3.x;
        ay += d0 * v0.y + d1 * v1.y + d2 * v2.y + d3 * v3.y;
        az += d0 * v0.z + d1 * v1.z + d2 * v2.z + d3 * v3.z;
        aw += d0 * v0.w + d1 * v1.w + d2 * v2.w + d3 * v3.w;
    }
    for (; i < e; i += 2) {
        int u = __ldg(&g_col[i]);
        float d = __ldg(&g_dinv[u]);
        float4 v = __ldg(&hs4[u * 16 + q]);
        ax += d * v.x; ay += d * v.y; az += d * v.z; aw += d * v.w;
    }
    ax += __shfl_xor_sync(0xffffffffu, ax, 16);
    ay += __shfl_xor_sync(0xffffffffu, ay, 16);
    az += __shfl_xor_sync(0xffffffffu, az, 16);
    aw += __shfl_xor_sync(0xffffffffu, aw, 16);
    float4 sv = __ldg(&hs4[w * 16 + q]);
    float dv = __ldg(&g_dinv[w]);
    ax += sv.x * dv; ay += sv.y * dv; az += sv.z * dv; aw += sv.w * dv;
    ax *= dv; ay *= dv; az *= dv; aw *= dv;
    if (bias) {
        float4 bv = __ldg(&((const float4*)bias)[q]);
        ax += bv.x; ay += bv.y; az += bv.z; aw += bv.w;
    }
    if (relu) {
        ax = fmaxf(ax, 0.f); ay = fmaxf(ay, 0.f);
        az = fmaxf(az, 0.f); aw = fmaxf(aw, 0.f);
    }
    if (lane < 16) ((float4*)out)[w * 16 + q] = make_float4(ax, ay, az, aw);
}

// ---------------- host launcher ----------------
extern "C" void kernel_launch(void* const* d_in, const int* in_sizes, int n_in,
                              void* d_out, int out_size) {
    const float* x  = (const float*)d_in[0];
    const int*   ei = (const int*)d_in[1];
    const float* W1 = (const float*)d_in[2];
    const float* b1 = (const float*)d_in[3];
    const float* W2 = (const float*)d_in[4];
    const float* b2 = (const float*)d_in[5];
    const float* W3 = (const float*)d_in[6];
    const float* b3 = (const float*)d_in[7];
    float* out = (float*)d_out;

    int hid   = in_sizes[3];            // 64
    int odim  = in_sizes[7];            // 112
    int indim = in_sizes[2] / hid;      // 128
    int n     = in_sizes[0] / indim;    // 100000
    int e     = in_sizes[1] / 2;        // 1600000
    const int* src = ei;
    const int* dst = ei + e;

    float *hs_p, *ag_p;
    cudaGetSymbolAddress((void**)&hs_p, g_hs);
    cudaGetSymbolAddress((void**)&ag_p, g_ag);

    int nb = (n + 1023) / 1024;
    int aggBlocks = (n * 32 + 255) / 256;
    int g128 = (n + 127) / 128;   // RG=2 CTAs (128 rows)
    int g64  = (n + 63) / 64;     // RG=1 CTAs (64 rows)

    // smem bytes: K * (Nn+8) * 2
    auto smem_sz = [](int K, int Nn) { return K * (Nn + 8) * 2; };

    zero_kernel<<<(n + 255) / 256, 256>>>(n);                          // 0
    hist_kernel<<<(e + 255) / 256, 256>>>(dst, e);                     // 1
    scan_blocks<<<nb, 1024>>>(n);                                      // 2
    // gemm1 is CSR-independent: at launch index 3 so ncu profiles it
    gemm_mma_kernel<8, 8, 2><<<g128, 128, smem_sz(128, 64)>>>(x, W1, hs_p, n, nullptr);
    finalize_kernel<<<(n + 255) / 256, 256>>>(n, nb);                  // 4
    scatter_kernel<<<(e + 255) / 256, 256>>>(src, dst, e);             // 5

    agg64_kernel<<<aggBlocks, 256>>>(hs_p, b1, ag_p, n, 1);            // 6
    gemm_mma_kernel<4, 8, 2><<<g128, 128, smem_sz(64, 64)>>>(ag_p, W2, hs_p, n, nullptr);
    agg64_kernel<<<aggBlocks, 256>>>(hs_p, b2, ag_p, n, 1);
    agg64_kernel<<<aggBlocks, 256>>>(ag_p, nullptr, hs_p, n, 0);
    gemm_mma_kernel<4, 14, 1><<<g64, 128, smem_sz(64, 112)>>>(hs_p, W3, out, n, b3);
}

// round 9
// speedup vs baseline: 1.1500x; 1.0175x over previous
#include <cuda_runtime.h>
#include <cuda_bf16.h>
#include <cuda_fp16.h>
#include <math.h>
#include <stdint.h>

#define NN 100000
#define EE 1600000
#define NB_MAX 128

// ---------------- device scratch ----------------
__device__ int    g_cnt[NN];
__device__ int    g_rowptr[NN + 1];
__device__ int    g_col[EE];
__device__ int    g_slot[EE];
__device__ int    g_bsum[NB_MAX];
__device__ float  g_dinv[NN];
__device__ __half g_hs16[(size_t)NN * 64];   // GEMM1/2 output (gathered)
__device__ __half g_ag16[(size_t)NN * 64];   // agg2 output (gathered by agg3)
__device__ float  g_ag32[(size_t)NN * 64];   // agg1 / agg3 output (GEMM A input)

// ---------------- preprocessing ----------------
__global__ void zero_kernel(int n) {
    int i = blockIdx.x * blockDim.x + threadIdx.x;
    if (i < n) g_cnt[i] = 0;
}
__global__ void hist_kernel(const int* __restrict__ dst, int e) {
    int i = blockIdx.x * blockDim.x + threadIdx.x;
    if (i < e) g_slot[i] = atomicAdd(&g_cnt[__ldg(&dst[i])], 1);
}
__global__ void scan_blocks(int n) {
    __shared__ int wsum[32];
    int tid = threadIdx.x, lane = tid & 31, wid = tid >> 5;
    int gid = blockIdx.x * 1024 + tid;
    int v = (gid < n) ? g_cnt[gid] : 0;
    int x = v;
    #pragma unroll
    for (int off = 1; off < 32; off <<= 1) {
        int t = __shfl_up_sync(0xffffffffu, x, off);
        if (lane >= off) x += t;
    }
    if (lane == 31) wsum[wid] = x;
    __syncthreads();
    if (wid == 0) {
        int s = wsum[lane];
        #pragma unroll
        for (int off = 1; off < 32; off <<= 1) {
            int t = __shfl_up_sync(0xffffffffu, s, off);
            if (lane >= off) s += t;
        }
        wsum[lane] = s;
    }
    __syncthreads();
    int incl = x + (wid > 0 ? wsum[wid - 1] : 0);
    if (gid < n) g_rowptr[gid] = incl - v;
    if (tid == 1023) g_bsum[blockIdx.x] = incl;
}
__global__ void finalize_kernel(int n, int nb) {
    __shared__ int sboff[NB_MAX];
    __shared__ int stot;
    int tid = threadIdx.x;
    if (tid < 32) {
        int base = tid * 4;
        int v0 = (base + 0 < nb) ? g_bsum[base + 0] : 0;
        int v1 = (base + 1 < nb) ? g_bsum[base + 1] : 0;
        int v2 = (base + 2 < nb) ? g_bsum[base + 2] : 0;
        int v3 = (base + 3 < nb) ? g_bsum[base + 3] : 0;
        int s0 = v0, s1 = s0 + v1, s2 = s1 + v2, s3 = s2 + v3;
        int c = s3;
        #pragma unroll
        for (int off = 1; off < 32; off <<= 1) {
            int t = __shfl_up_sync(0xffffffffu, c, off);
            if (tid >= off) c += t;
        }
        int excl = c - s3;
        sboff[base + 0] = excl;
        sboff[base + 1] = excl + s0;
        sboff[base + 2] = excl + s1;
        sboff[base + 3] = excl + s2;
        if (tid == 31) stot = c;
    }
    __syncthreads();
    int i = blockIdx.x * blockDim.x + tid;
    if (i < n) {
        g_rowptr[i] += sboff[i >> 10];
        g_dinv[i] = rsqrtf((float)(g_cnt[i] + 1));
    }
    if (blockIdx.x == 0 && tid == 0) g_rowptr[n] = stot;
}
__global__ void scatter_kernel(const int* __restrict__ src,
                               const int* __restrict__ dst, int e) {
    int i = blockIdx.x * blockDim.x + threadIdx.x;
    if (i < e) {
        int d = __ldg(&dst[i]);
        g_col[g_rowptr[d] + g_slot[i]] = __ldg(&src[i]);
    }
}

// ---------------- fp16 mma helpers ----------------
__device__ __forceinline__ uint32_t h2_hi(float2 v) {
    __half2 h = __floats2half2_rn(v.x, v.y);
    return *reinterpret_cast<uint32_t*>(&h);
}
__device__ __forceinline__ uint32_t h2_lo(float2 v, uint32_t hbits) {
    __half2 h = *reinterpret_cast<__half2*>(&hbits);
    float2 b = __half22float2(h);
    __half2 l = __floats2half2_rn(v.x - b.x, v.y - b.y);
    return *reinterpret_cast<uint32_t*>(&l);
}
__device__ __forceinline__ void mma_f16(float* c, uint32_t a0, uint32_t a1,
                                        uint32_t a2, uint32_t a3,
                                        uint32_t b0, uint32_t b1) {
    asm volatile(
        "mma.sync.aligned.m16n8k16.row.col.f32.f16.f16.f32 "
        "{%0,%1,%2,%3}, {%4,%5,%6,%7}, {%8,%9}, {%0,%1,%2,%3};"
        : "+f"(c[0]), "+f"(c[1]), "+f"(c[2]), "+f"(c[3])
        : "r"(a0), "r"(a1), "r"(a2), "r"(a3), "r"(b0), "r"(b1));
}
__device__ __forceinline__ void ldsm_x4_trans(uint32_t& r0, uint32_t& r1,
                                              uint32_t& r2, uint32_t& r3, uint32_t a) {
    asm volatile("ldmatrix.sync.aligned.m8n8.x4.trans.shared.b16 {%0,%1,%2,%3}, [%4];"
                 : "=r"(r0), "=r"(r1), "=r"(r2), "=r"(r3) : "r"(a));
}

// ---------------- GEMM: fp16 2-pass (A split, B single), RG row-groups/warp ----
// OUTH=1: out is __half (no bias). OUTH=0: out float (+ optional bias).
template <int KS, int NT, int RG, int OUTH>
__global__ void __launch_bounds__(128)
gemm_mma_kernel(const float* __restrict__ X, const float* __restrict__ W,
                void* __restrict__ outv, int M, const float* __restrict__ bias) {
    constexpr int K  = KS * 16;
    constexpr int Nn = NT * 8;
    constexpr int PB = Nn + 8;
    constexpr int MT = 64 * RG;
    extern __shared__ __half wS[];

    int tid = threadIdx.x, lane = tid & 31, wid = tid >> 5;
    int rowbase = blockIdx.x * MT;

    constexpr int N4 = Nn / 4;
    #pragma unroll
    for (int idx = tid; idx < K * N4; idx += 128) {
        int k = idx / N4;
        int n4 = (idx - k * N4) * 4;
        float4 v = __ldg((const float4*)(W + (size_t)k * Nn + n4));
        *(__half2*)(wS + k * PB + n4)     = __floats2half2_rn(v.x, v.y);
        *(__half2*)(wS + k * PB + n4 + 2) = __floats2half2_rn(v.z, v.w);
    }
    __syncthreads();

    int gp = lane >> 2, tig = lane & 3;
    const float* xA[RG];
    const float* xB[RG];
    int rA[RG], rB[RG];
    #pragma unroll
    for (int rg = 0; rg < RG; rg++) {
        rA[rg] = rowbase + wid * (16 * RG) + rg * 16 + gp;
        rB[rg] = rA[rg] + 8;
        xA[rg] = X + (size_t)min(rA[rg], M - 1) * K + tig * 2;
        xB[rg] = X + (size_t)min(rB[rg], M - 1) * K + tig * 2;
    }

    int kRow = (lane & 7) + (((lane >> 3) & 1) << 3);
    int nCol = (lane >> 4) << 3;
    uint32_t wBase = (uint32_t)__cvta_generic_to_shared(wS) +
                     (uint32_t)((kRow * PB + nCol) * 2);

    float acc[RG][NT][4];
    #pragma unroll
    for (int rg = 0; rg < RG; rg++)
        #pragma unroll
        for (int t = 0; t < NT; t++) {
            acc[rg][t][0] = 0.f; acc[rg][t][1] = 0.f;
            acc[rg][t][2] = 0.f; acc[rg][t][3] = 0.f;
        }

    #pragma unroll
    for (int kt = 0; kt < KS; kt++) {
        int ko = kt * 16;
        uint32_t ah[RG][4], al[RG][4];
        #pragma unroll
        for (int rg = 0; rg < RG; rg++) {
            float2 p0 = __ldg((const float2*)(xA[rg] + ko));
            float2 p1 = __ldg((const float2*)(xA[rg] + ko + 8));
            float2 p2 = __ldg((const float2*)(xB[rg] + ko));
            float2 p3 = __ldg((const float2*)(xB[rg] + ko + 8));
            ah[rg][0] = h2_hi(p0); al[rg][0] = h2_lo(p0, ah[rg][0]);
            ah[rg][1] = h2_hi(p2); al[rg][1] = h2_lo(p2, ah[rg][1]);
            ah[rg][2] = h2_hi(p1); al[rg][2] = h2_lo(p1, ah[rg][2]);
            ah[rg][3] = h2_hi(p3); al[rg][3] = h2_lo(p3, ah[rg][3]);
        }
        uint32_t kByte = (uint32_t)(ko * PB * 2);
        #pragma unroll
        for (int nt2 = 0; nt2 < NT / 2; nt2++) {
            uint32_t b0, b1, b2, b3;
            ldsm_x4_trans(b0, b1, b2, b3, wBase + kByte + (uint32_t)(nt2 * 16 * 2));
            #pragma unroll
            for (int rg = 0; rg < RG; rg++) {
                mma_f16(acc[rg][2 * nt2],     ah[rg][0], ah[rg][1], ah[rg][2], ah[rg][3], b0, b1);
                mma_f16(acc[rg][2 * nt2],     al[rg][0], al[rg][1], al[rg][2], al[rg][3], b0, b1);
                mma_f16(acc[rg][2 * nt2 + 1], ah[rg][0], ah[rg][1], ah[rg][2], ah[rg][3], b2, b3);
                mma_f16(acc[rg][2 * nt2 + 1], al[rg][0], al[rg][1], al[rg][2], al[rg][3], b2, b3);
            }
        }
    }

    #pragma unroll
    for (int rg = 0; rg < RG; rg++) {
        #pragma unroll
        for (int nt = 0; nt < NT; nt++) {
            int col = nt * 8 + tig * 2;
            if (OUTH) {
                __half* outh = (__half*)outv;
                if (rA[rg] < M)
                    *(__half2*)(outh + (size_t)rA[rg] * Nn + col) =
                        __floats2half2_rn(acc[rg][nt][0], acc[rg][nt][1]);
                if (rB[rg] < M)
                    *(__half2*)(outh + (size_t)rB[rg] * Nn + col) =
                        __floats2half2_rn(acc[rg][nt][2], acc[rg][nt][3]);
            } else {
                float* outf = (float*)outv;
                float bx = 0.f, by = 0.f;
                if (bias) {
                    float2 bv = __ldg((const float2*)&bias[col]);
                    bx = bv.x; by = bv.y;
                }
                if (rA[rg] < M)
                    *(float2*)(outf + (size_t)rA[rg] * Nn + col) =
                        make_float2(acc[rg][nt][0] + bx, acc[rg][nt][1] + by);
                if (rB[rg] < M)
                    *(float2*)(outf + (size_t)rB[rg] * Nn + col) =
                        make_float2(acc[rg][nt][2] + bx, acc[rg][nt][3] + by);
            }
        }
    }
}

// ---------------- aggregation over fp16 rows (128B = 1 L2 line per edge) --------
// 8 lanes/edge, 4 edges concurrent, fp32 accumulate.
// out[v] = dinv[v]*( sum_u dinv[u]*in[u] + dinv[v]*in[v] ) + bias?, relu?
template <int OUTH, int RELU, int BIAS>
__global__ void agg_kernel(const __half* __restrict__ hs,
                           const float* __restrict__ bias,
                           void* __restrict__ outv, int n) {
    int w = (blockIdx.x * blockDim.x + threadIdx.x) >> 5;
    if (w >= n) return;
    int lane = threadIdx.x & 31;
    int quarter = lane >> 3;   // which edge in the group of 4
    int sub = lane & 7;        // which 8-channel chunk
    const uint4* hrow = (const uint4*)hs;   // 8 uint4 per 64-ch row

    float acc[8];
    #pragma unroll
    for (int j = 0; j < 8; j++) acc[j] = 0.f;

    int s = g_rowptr[w], e = g_rowptr[w + 1];
    int i = s + quarter;
    for (; i + 4 < e; i += 8) {
        int u0 = __ldg(&g_col[i]);
        int u1 = __ldg(&g_col[i + 4]);
        float d0 = __ldg(&g_dinv[u0]);
        float d1 = __ldg(&g_dinv[u1]);
        uint4 v0 = __ldg(&hrow[(size_t)u0 * 8 + sub]);
        uint4 v1 = __ldg(&hrow[(size_t)u1 * 8 + sub]);
        const __half2* h0 = (const __half2*)&v0;
        const __half2* h1 = (const __half2*)&v1;
        #pragma unroll
        for (int j = 0; j < 4; j++) {
            float2 f0 = __half22float2(h0[j]);
            float2 f1 = __half22float2(h1[j]);
            acc[2 * j]     += d0 * f0.x + d1 * f1.x;
            acc[2 * j + 1] += d0 * f0.y + d1 * f1.y;
        }
    }
    if (i < e) {
        int u = __ldg(&g_col[i]);
        float d = __ldg(&g_dinv[u]);
        uint4 v = __ldg(&hrow[(size_t)u * 8 + sub]);
        const __half2* h = (const __half2*)&v;
        #pragma unroll
        for (int j = 0; j < 4; j++) {
            float2 f = __half22float2(h[j]);
            acc[2 * j]     += d * f.x;
            acc[2 * j + 1] += d * f.y;
        }
    }
    // self-loop on quarter 0 only
    if (quarter == 0) {
        float dv = __ldg(&g_dinv[w]);
        uint4 v = __ldg(&hrow[(size_t)w * 8 + sub]);
        const __half2* h = (const __half2*)&v;
        #pragma unroll
        for (int j = 0; j < 4; j++) {
            float2 f = __half22float2(h[j]);
            acc[2 * j]     += dv * f.x;
            acc[2 * j + 1] += dv * f.y;
        }
    }
    // combine 4 quarters
    #pragma unroll
    for (int j = 0; j < 8; j++) {
        acc[j] += __shfl_xor_sync(0xffffffffu, acc[j], 8);
        acc[j] += __shfl_xor_sync(0xffffffffu, acc[j], 16);
    }
    if (lane < 8) {
        float dv = __ldg(&g_dinv[w]);
        #pragma unroll
        for (int j = 0; j < 8; j++) acc[j] *= dv;
        if (BIAS) {
            float4 b0 = __ldg((const float4*)&bias[sub * 8]);
            float4 b1 = __ldg((const float4*)&bias[sub * 8 + 4]);
            acc[0] += b0.x; acc[1] += b0.y; acc[2] += b0.z; acc[3] += b0.w;
            acc[4] += b1.x; acc[5] += b1.y; acc[6] += b1.z; acc[7] += b1.w;
        }
        if (RELU) {
            #pragma unroll
            for (int j = 0; j < 8; j++) acc[j] = fmaxf(acc[j], 0.f);
        }
        if (OUTH) {
            __half2 o[4];
            #pragma unroll
            for (int j = 0; j < 4; j++)
                o[j] = __floats2half2_rn(acc[2 * j], acc[2 * j + 1]);
            ((uint4*)outv)[(size_t)w * 8 + sub] = *(uint4*)o;
        } else {
            float4* of = (float4*)outv;
            of[(size_t)w * 16 + sub * 2]     = make_float4(acc[0], acc[1], acc[2], acc[3]);
            of[(size_t)w * 16 + sub * 2 + 1] = make_float4(acc[4], acc[5], acc[6], acc[7]);
        }
    }
}

// ---------------- host launcher ----------------
extern "C" void kernel_launch(void* const* d_in, const int* in_sizes, int n_in,
                              void* d_out, int out_size) {
    const float* x  = (const float*)d_in[0];
    const int*   ei = (const int*)d_in[1];
    const float* W1 = (const float*)d_in[2];
    const float* b1 = (const float*)d_in[3];
    const float* W2 = (const float*)d_in[4];
    const float* b2 = (const float*)d_in[5];
    const float* W3 = (const float*)d_in[6];
    const float* b3 = (const float*)d_in[7];
    float* out = (float*)d_out;

    int hid   = in_sizes[3];            // 64
    int odim  = in_sizes[7];            // 112
    int indim = in_sizes[2] / hid;      // 128
    int n     = in_sizes[0] / indim;    // 100000
    int e     = in_sizes[1] / 2;        // 1600000
    const int* src = ei;
    const int* dst = ei + e;

    __half *hs16_p, *ag16_p;
    float  *ag32_p;
    cudaGetSymbolAddress((void**)&hs16_p, g_hs16);
    cudaGetSymbolAddress((void**)&ag16_p, g_ag16);
    cudaGetSymbolAddress((void**)&ag32_p, g_ag32);

    int nb = (n + 1023) / 1024;
    int aggBlocks = (n * 32 + 255) / 256;
    int g128 = (n + 127) / 128;
    int g64  = (n + 63) / 64;

    auto smem_sz = [](int K, int Nn) { return K * (Nn + 8) * 2; };

    zero_kernel<<<(n + 255) / 256, 256>>>(n);                          // 0
    hist_kernel<<<(e + 255) / 256, 256>>>(dst, e);                     // 1
    scan_blocks<<<nb, 1024>>>(n);                                      // 2
    // gemm1 (CSR-independent) at launch index 3 for ncu
    gemm_mma_kernel<8, 8, 2, 1><<<g128, 128, smem_sz(128, 64)>>>(x, W1, hs16_p, n, nullptr);
    finalize_kernel<<<(n + 255) / 256, 256>>>(n, nb);                  // 4
    scatter_kernel<<<(e + 255) / 256, 256>>>(src, dst, e);             // 5

    // agg1: hs16 -> ag32 (+b1, relu)
    agg_kernel<0, 1, 1><<<aggBlocks, 256>>>(hs16_p, b1, ag32_p, n);    // 6
    // gemm2: ag32 @ W2 -> hs16
    gemm_mma_kernel<4, 8, 2, 1><<<g128, 128, smem_sz(64, 64)>>>(ag32_p, W2, hs16_p, n, nullptr);
    // agg2: hs16 -> ag16 (+b2, relu)
    agg_kernel<1, 1, 1><<<aggBlocks, 256>>>(hs16_p, b2, ag16_p, n);
    // agg3: ag16 -> ag32 (no bias/relu)
    agg_kernel<0, 0, 0><<<aggBlocks, 256>>>(ag16_p, nullptr, ag32_p, n);
    // gemm3: ag32 @ W3 + b3 -> out (fp32)
    gemm_mma_kernel<4, 14, 1, 0><<<g64, 128, smem_sz(64, 112)>>>(ag32_p, W3, out, n, b3);
}